// round 15
// baseline (speedup 1.0000x reference)
#include <cuda_runtime.h>
#include <stdint.h>

// PicMix: output = two index-function masks, no input read.
// Flattened: [mask_a (8,12,512,512) fp32][mask_b same]. 192 planes of 512x512.
// group g = (ch%12)/3; isB = second mask.
//   g0: a=1,b=0 | g1: a=(i%2==j%2) | g2: a=i%2 | g3: a=j%2 ; b = complement.
// Each float4 covers j..j+3 (even start) -> lanes are (even,odd,even,odd).
//
// FINAL: 12288 CTAs x 256 thr x 4 float4/thread — measured sweep optimum.
// ncu over six repeat runs: {27.71, 28.32, 27.81, 28.00, 28.99, 27.58}us
// (mean 28.1, sigma ~0.5); harness 30.9-31.5. Thread stride = 256 f4 =
// exactly 2 rows, so row parity (and the store value) is constant per
// thread: decode once, 4x STG.E.128 at immediate offsets.
//
// Complete sweep (14 benched rounds):
//   grid/unroll: 49152x1 | 24576x2 | 12288x4* | 6144x4@512t | 3072x16 | 1536x32
//   vector:      STG.128* | STG.256 (neutral)
//   policy:      default* | .cs (worse)
//   path:        SM STG*  | TMA bulk async (neutral-worse)
//   block size:  256* | 512 (neutral)
// All mechanisms plateau at 27.6-30.7us ncu / 58-65% DRAM: the chip-wide,
// path-independent LTS store ceiling (~7.2 TB/s L2-side, ~6300 B/cyc).
// The 201.3 MB output is irreducible (exact fp32 0/1 planes, poisoned
// buffer, 1.0f not byte-uniform so no memset path, CE shares the LTS cap).
// Run-to-run variance of this config exceeds every config-to-config delta
// -> the kernel is at the hardware floor; further changes fit noise.

static constexpr int PLANE_F4         = 65536;  // 512*512/4
static constexpr int BLOCKS_PER_PLANE = 64;
static constexpr int F4_PER_BLOCK     = PLANE_F4 / BLOCKS_PER_PLANE; // 1024
static constexpr int THREADS          = 256;
static constexpr int F4_PER_THREAD    = F4_PER_BLOCK / THREADS;      // 4

__global__ void __launch_bounds__(THREADS) picmix_kernel(float4* __restrict__ out) {
    int plane = blockIdx.x >> 6;        // BLOCKS_PER_PLANE = 64
    int seg   = blockIdx.x & 63;

    int base = plane * PLANE_F4 + seg * F4_PER_BLOCK + threadIdx.x;
    int ip   = (base >> 7) & 1;         // row parity; invariant across strided stores

    int isB = plane >= 96;              // 96 planes per mask
    int pin = isB ? plane - 96 : plane;
    int ch  = pin % 12;
    int g   = ch * 0x5556 >> 16;        // ch/3 for ch in [0,12)

    float e, o;                         // even-j value, odd-j value
    if (g == 0) {
        e = o = isB ? 0.0f : 1.0f;
    } else if (g == 1) {
        float s = (ip == 0) ? 1.0f : 0.0f;   // mask_a even lane
        e = isB ? 1.0f - s : s;
        o = 1.0f - e;
    } else if (g == 2) {
        float v = (float)ip;
        e = o = isB ? 1.0f - v : v;
    } else {
        e = isB ? 1.0f : 0.0f;
        o = 1.0f - e;
    }

    float4 v4 = make_float4(e, o, e, o);
    float4* p = out + base;
    #pragma unroll
    for (int k = 0; k < F4_PER_THREAD; k++) {
        p[k * THREADS] = v4;            // stride 256 f4 = 4KB = 2 rows
    }
}

extern "C" void kernel_launch(void* const* d_in, const int* in_sizes, int n_in,
                              void* d_out, int out_size) {
    (void)d_in; (void)in_sizes; (void)n_in; (void)out_size;
    // out_size = 50,331,648 fp32 = 192 planes * 65536 f4
    int blocks = 192 * BLOCKS_PER_PLANE;  // 12288
    picmix_kernel<<<blocks, THREADS>>>((float4*)d_out);
}

// round 16
// speedup vs baseline: 1.0010x; 1.0010x over previous
#include <cuda_runtime.h>
#include <stdint.h>

// PicMix: output = two index-function masks, no input read.
// Flattened: [mask_a (8,12,512,512) fp32][mask_b same]. 192 planes of 512x512.
// group g = (ch%12)/3; isB = second mask.
//   g0: a=1,b=0 | g1: a=(i%2==j%2) | g2: a=i%2 | g3: a=j%2 ; b = complement.
// Each float4 covers j..j+3 (even start) -> lanes are (even,odd,even,odd).
//
// FINAL: 12288 CTAs x 256 thr x 4 float4/thread — measured sweep optimum.
// ncu over seven repeat runs: {27.71, 28.32, 27.81, 28.00, 28.99, 27.58,
// 27.68}us (mean 28.0, sigma ~0.5); harness stable at 31.2-31.5.
// Thread stride = 256 f4 = exactly 2 rows, so row parity (and the store
// value) is constant per thread: decode once, 4x STG.E.128 at immediate
// offsets.
//
// Complete sweep (15 benched rounds):
//   grid/unroll: 49152x1 | 24576x2 | 12288x4* | 6144x4@512t | 3072x16 | 1536x32
//   vector:      STG.128* | STG.256 (neutral)
//   policy:      default* | .cs (worse)
//   path:        SM STG*  | TMA bulk async (neutral-worse)
//   block size:  256* | 512 (neutral)
// All mechanisms plateau at 27.6-30.7us ncu / 58-65% DRAM: the chip-wide,
// path-independent LTS store ceiling (~7.2 TB/s L2-side, ~6300 B/cyc).
// The 201.3 MB output is irreducible (exact fp32 0/1 planes, poisoned
// buffer, 1.0f not byte-uniform so no memset path, CE shares the LTS cap).
// Run-to-run variance of this config exceeds every config-to-config delta
// -> the kernel is at the hardware floor.

static constexpr int PLANE_F4         = 65536;  // 512*512/4
static constexpr int BLOCKS_PER_PLANE = 64;
static constexpr int F4_PER_BLOCK     = PLANE_F4 / BLOCKS_PER_PLANE; // 1024
static constexpr int THREADS          = 256;
static constexpr int F4_PER_THREAD    = F4_PER_BLOCK / THREADS;      // 4

__global__ void __launch_bounds__(THREADS) picmix_kernel(float4* __restrict__ out) {
    int plane = blockIdx.x >> 6;        // BLOCKS_PER_PLANE = 64
    int seg   = blockIdx.x & 63;

    int base = plane * PLANE_F4 + seg * F4_PER_BLOCK + threadIdx.x;
    int ip   = (base >> 7) & 1;         // row parity; invariant across strided stores

    int isB = plane >= 96;              // 96 planes per mask
    int pin = isB ? plane - 96 : plane;
    int ch  = pin % 12;
    int g   = ch * 0x5556 >> 16;        // ch/3 for ch in [0,12)

    float e, o;                         // even-j value, odd-j value
    if (g == 0) {
        e = o = isB ? 0.0f : 1.0f;
    } else if (g == 1) {
        float s = (ip == 0) ? 1.0f : 0.0f;   // mask_a even lane
        e = isB ? 1.0f - s : s;
        o = 1.0f - e;
    } else if (g == 2) {
        float v = (float)ip;
        e = o = isB ? 1.0f - v : v;
    } else {
        e = isB ? 1.0f : 0.0f;
        o = 1.0f - e;
    }

    float4 v4 = make_float4(e, o, e, o);
    float4* p = out + base;
    #pragma unroll
    for (int k = 0; k < F4_PER_THREAD; k++) {
        p[k * THREADS] = v4;            // stride 256 f4 = 4KB = 2 rows
    }
}

extern "C" void kernel_launch(void* const* d_in, const int* in_sizes, int n_in,
                              void* d_out, int out_size) {
    (void)d_in; (void)in_sizes; (void)n_in; (void)out_size;
    // out_size = 50,331,648 fp32 = 192 planes * 65536 f4
    int blocks = 192 * BLOCKS_PER_PLANE;  // 12288
    picmix_kernel<<<blocks, THREADS>>>((float4*)d_out);
}